// round 16
// baseline (speedup 1.0000x reference)
#include <cuda_runtime.h>
#include <cstdint>

#define TPB 512
#define SAS 20              // A row stride (16+4) words
#define ABUFW 2560          // 128*20 words per A buffer
#define BBUFW 2560          // covers NT(128*20) and NN(16*136)

// B=4, U=64, V=256, DIM=768, CODE=384, INNER=512, HEADS=8, HD=64

struct Params {
    const float *recv, *codes, *send;
    const float *lnrg, *lnrb, *lnsg, *lnsb;
    const float *Wq, *bq, *Wmq, *Wk, *bk, *Wmk;
    const float *Wv, *bv, *Wmv, *We, *be, *Wme, *gamma;
    float* out;
    int nb;
};

// ---------------- Scratch (device globals; no allocs) ----------------
__device__ __align__(16) float g_r  [256 * 768];
__device__ __align__(16) float g_s  [1024 * 768];
__device__ __align__(16) float g_rq [256 * 768];
__device__ __align__(16) float g_mqp[3 * 196608];
__device__ __align__(16) float g_mkp[3 * 196608];
__device__ __align__(16) float g_mvp[3 * 196608];
__device__ __align__(16) float g_mep[3 * 131072];
__device__ __align__(16) float g_q  [256 * 512];
__device__ __align__(16) float g_qbk[256 * 8];
__device__ __align__(16) float g_Ak [4 * 512 * 768];
__device__ __align__(16) float g_w  [4 * 512 * 256];
__device__ __align__(16) float g_Tm [8 * 256 * 768];
__device__ __align__(16) float g_msg[256 * 512];
#define QP 131072
#define WP 524288
#define OP 196608
__device__ __align__(16) float g_qp[16 * QP];
__device__ __align__(16) float g_wp[4 * WP];

__device__ unsigned g_barcnt = 0;
__device__ unsigned g_bargen = 0;

__device__ __forceinline__ void grid_bar(int nb) {
    __syncthreads();
    if (threadIdx.x == 0) {
        __threadfence();
        unsigned gen = *(volatile unsigned*)&g_bargen;
        unsigned t = atomicAdd(&g_barcnt, 1u);
        if (t == (unsigned)(nb - 1)) {
            atomicExch(&g_barcnt, 0u);
            __threadfence();
            atomicExch(&g_bargen, gen + 1u);
        } else {
            while (*(volatile unsigned*)&g_bargen == gen) { __nanosleep(32); }
        }
        __threadfence();
    }
    __syncthreads();
}

// ---------------- helpers ----------------
__device__ __forceinline__ void mma8(float* c, const uint32_t* a, const uint32_t* b) {
    asm volatile(
        "mma.sync.aligned.m16n8k8.row.col.f32.tf32.tf32.f32 "
        "{%0,%1,%2,%3}, {%4,%5,%6,%7}, {%8,%9}, {%0,%1,%2,%3};"
        : "+f"(c[0]), "+f"(c[1]), "+f"(c[2]), "+f"(c[3])
        : "r"(a[0]), "r"(a[1]), "r"(a[2]), "r"(a[3]), "r"(b[0]), "r"(b[1]));
}
__device__ __forceinline__ uint32_t f2tf(float x) {
    uint32_t u;
    asm("cvt.rna.tf32.f32 %0, %1;" : "=r"(u) : "f"(x));
    return u;
}
__device__ __forceinline__ float4 ld4(const float* p) { return *(const float4*)p; }

// ---- block 128xNTILE tf32 GEMM, 512 threads, LDG.128->reg->STS.128, 2-deep ----
// C(m,n) = sum_k A(m,k)*B(k,n); K%16==0.
// la4(m,k) -> float4 A(m, k..k+3).
// BT=false: lb4(k,n) -> float4 B(k, n..n+3); BT=true: lb4(n,k) -> float4 B(n, k..k+3).
template<bool BT, int NTILE, class LA, class LB, class EP>
__device__ __forceinline__ void gemm_ld(int K, uint32_t* smA, uint32_t* smB,
                                        LA la4, LB lb4, EP ep) {
    constexpr int NJ = NTILE / 32;
    constexpr int SB = BT ? 20 : (NTILE + 8);
    const int tid = threadIdx.x;
    const int l = tid & 31, g = l >> 2, t = l & 3;
    const int wid = tid >> 5;
    const int wm0 = (wid >> 2) * 32, wn0 = (wid & 3) * (NTILE / 4);
    const int ns = K / 16;

    const int ar = tid >> 2, ac = (tid & 3) * 4;                  // A fill
    const int btn = tid >> 2, btk = (tid & 3) * 4;                // B NT fill
    const bool bact = BT ? true : (tid < NTILE * 4);              // B NN active
    const int bk = BT ? 0 : tid / (NTILE / 4);
    const int bn = BT ? 0 : (tid % (NTILE / 4)) * 4;

    float acc[2][NJ][4];
    #pragma unroll
    for (int i = 0; i < 2; i++)
        #pragma unroll
        for (int j = 0; j < NJ; j++)
            #pragma unroll
            for (int e = 0; e < 4; e++) acc[i][j][e] = 0.f;

    float4 ra = la4(ar, ac);
    float4 rb = make_float4(0.f, 0.f, 0.f, 0.f);
    if (BT) rb = lb4(btn, btk); else if (bact) rb = lb4(bk, bn);

    auto sts = [&](int p) {
        uint32_t* A = smA + p * ABUFW;
        uint32_t* B = smB + p * BBUFW;
        uint4 ca; ca.x = f2tf(ra.x); ca.y = f2tf(ra.y); ca.z = f2tf(ra.z); ca.w = f2tf(ra.w);
        *(uint4*)&A[ar * SAS + ac] = ca;
        if (BT) {
            uint4 cb; cb.x = f2tf(rb.x); cb.y = f2tf(rb.y); cb.z = f2tf(rb.z); cb.w = f2tf(rb.w);
            *(uint4*)&B[btn * 20 + btk] = cb;
        } else if (bact) {
            uint4 cb; cb.x = f2tf(rb.x); cb.y = f2tf(rb.y); cb.z = f2tf(rb.z); cb.w = f2tf(rb.w);
            *(uint4*)&B[bk * SB + bn] = cb;
        }
    };

    sts(0);
    __syncthreads();

    for (int s = 0; s < ns; s++) {
        if (s + 1 < ns) {
            int k0 = (s + 1) * 16;
            ra = la4(ar, k0 + ac);
            if (BT) rb = lb4(btn, k0 + btk); else if (bact) rb = lb4(k0 + bk, bn);
        }
        const uint32_t* __restrict__ A = smA + (s & 1) * ABUFW;
        const uint32_t* __restrict__ B = smB + (s & 1) * BBUFW;
        #pragma unroll
        for (int kk = 0; kk < 16; kk += 8) {
            uint32_t af[2][4], bf[NJ][2];
            #pragma unroll
            for (int mi = 0; mi < 2; mi++) {
                int mb = wm0 + mi * 16;
                af[mi][0] = A[(mb + g) * SAS + kk + t];
                af[mi][1] = A[(mb + 8 + g) * SAS + kk + t];
                af[mi][2] = A[(mb + g) * SAS + kk + t + 4];
                af[mi][3] = A[(mb + 8 + g) * SAS + kk + t + 4];
            }
            #pragma unroll
            for (int nj = 0; nj < NJ; nj++) {
                int nn = wn0 + nj * 8 + g;
                if (BT) {
                    bf[nj][0] = B[nn * 20 + kk + t];
                    bf[nj][1] = B[nn * 20 + kk + t + 4];
                } else {
                    bf[nj][0] = B[(kk + t) * SB + nn];
                    bf[nj][1] = B[(kk + t + 4) * SB + nn];
                }
            }
            #pragma unroll
            for (int mi = 0; mi < 2; mi++)
                #pragma unroll
                for (int nj = 0; nj < NJ; nj++)
                    mma8(acc[mi][nj], af[mi], bf[nj]);
        }
        if (s + 1 < ns) sts((s + 1) & 1);
        __syncthreads();
    }

    #pragma unroll
    for (int mi = 0; mi < 2; mi++)
        #pragma unroll
        for (int nj = 0; nj < NJ; nj++) {
            int r = wm0 + mi * 16 + g, c = wn0 + nj * 8 + 2 * t;
            ep(r,     c,     acc[mi][nj][0]);
            ep(r,     c + 1, acc[mi][nj][1]);
            ep(r + 8, c,     acc[mi][nj][2]);
            ep(r + 8, c + 1, acc[mi][nj][3]);
        }
}

// ---------------- warp LayerNorm over a 768-row ----------------
__device__ __forceinline__ void ln_row(const float* __restrict__ x,
                                       const float* __restrict__ g,
                                       const float* __restrict__ b,
                                       float* __restrict__ o) {
    int lane = threadIdx.x & 31;
    float v[24];
    float s = 0.f, q = 0.f;
    #pragma unroll
    for (int i = 0; i < 24; i++) {
        v[i] = x[lane + 32 * i];
        s += v[i];
        q += v[i] * v[i];
    }
    #pragma unroll
    for (int off = 16; off; off >>= 1) {
        s += __shfl_xor_sync(0xffffffffu, s, off);
        q += __shfl_xor_sync(0xffffffffu, q, off);
    }
    float mu  = s * (1.f / 768.f);
    float inv = rsqrtf(q * (1.f / 768.f) - mu * mu + 1e-5f);
    #pragma unroll
    for (int i = 0; i < 24; i++) {
        int idx = lane + 32 * i;
        o[idx] = (v[i] - mu) * inv * g[idx] + b[idx];
    }
}

// ---------------- The single persistent kernel: 1 block/SM, 512 threads ----
__global__ void __launch_bounds__(TPB, 1) fused_kernel(Params P) {
    __shared__ __align__(16) uint32_t smA[2 * ABUFW];
    __shared__ __align__(16) uint32_t smB[2 * BBUFW];
    const int nb = P.nb;
    const int bid = blockIdx.x;
    const int wglob = bid * 16 + (threadIdx.x >> 5);
    const int nwarp = nb * 16;
    const int lane32 = threadIdx.x & 31;
    const int nth = nwarp * 32;
    const int gt = wglob * 32 + lane32;

    // ---- S0: LayerNorms ----
    for (int r = wglob; r < 1280; r += nwarp) {
        if (r < 256) ln_row(P.recv + r * 768, P.lnrg, P.lnrb, g_r + r * 768);
        else {
            int rr = r - 256;
            ln_row(P.send + rr * 768, P.lnsg, P.lnsb, g_s + rr * 768);
        }
    }
    grid_bar(nb);

    // ---- S1: 4 modulation GEMMs, K split x3 (K=128 -> 8 steps): 132 tiles ----
    for (int tt = bid; tt < 132; tt += nb) {
        if (tt < 108) {
            int sel = tt / 36, r = tt % 36;
            int kp = r / 12, lt = r % 12;
            const float* W = sel == 0 ? P.Wmq : (sel == 1 ? P.Wmk : P.Wmv);
            float* O = (sel == 0 ? g_mqp : (sel == 1 ? g_mkp : g_mvp)) + kp * 196608;
            int m0 = (lt % 2) * 128, n0 = (lt / 2) * 128, kb = kp * 128;
            gemm_ld<false, 128>(128, smA, smB,
                [&](int m, int k) { return ld4(&P.codes[(m0 + m) * 384 + kb + k]); },
                [&](int k, int n) { return ld4(&W[(kb + k) * 768 + n0 + n]); },
                [&](int m, int n, float a) { O[(long)(m0 + m) * 768 + n0 + n] = a; });
        } else {
            int r = tt - 108;
            int kp = r / 8, lt = r % 8;
            float* O = g_mep + kp * 131072;
            int m0 = (lt & 1) * 128, n0 = (lt >> 1) * 128, kb = kp * 128;
            gemm_ld<false, 128>(128, smA, smB,
                [&](int m, int k) { return ld4(&P.codes[(m0 + m) * 384 + kb + k]); },
                [&](int k, int n) { return ld4(&P.Wme[(kb + k) * 512 + n0 + n]); },
                [&](int m, int n, float a) { O[(long)(m0 + m) * 512 + n0 + n] = a; });
        }
    }
    grid_bar(nb);

    // ---- S1b: rq = r * (1 + mqp0+mqp1+mqp2) ----
    for (int i = gt; i < 49152; i += nth) {
        long idx = (long)i * 4;
        float4 a = ld4(&g_mqp[idx]), b = ld4(&g_mqp[196608 + idx]);
        float4 c = ld4(&g_mqp[2 * 196608 + idx]), r = ld4(&g_r[idx]);
        float4 o;
        o.x = r.x * (1.f + a.x + b.x + c.x); o.y = r.y * (1.f + a.y + b.y + c.y);
        o.z = r.z * (1.f + a.z + b.z + c.z); o.w = r.w * (1.f + a.w + b.w + c.w);
        *(float4*)&g_rq[idx] = o;
    }
    grid_bar(nb);

    // ---- S2: q partials, K split x16 (K=48 -> 3 steps): 128 tiles ----
    for (int tt = bid; tt < 128; tt += nb) {
        int kp = tt >> 3, lt = tt & 7;
        int m0 = (lt & 1) * 128, n0 = (lt >> 1) * 128, kb = kp * 48;
        gemm_ld<false, 128>(48, smA, smB,
            [&](int m, int k) { return ld4(&g_rq[(m0 + m) * 768 + kb + k]); },
            [&](int k, int n) { return ld4(&P.Wq[(kb + k) * 512 + n0 + n]); },
            [&](int m, int n, float a) { g_qp[kp * QP + (m0 + m) * 512 + n0 + n] = a; });
    }
    grid_bar(nb);

    // ---- S2b: q = sum(16 partials)+bq ; qbk = q_h . bk_h ----
    for (int w = wglob; w < 2048; w += nwarp) {
        int bu = w >> 3, h = w & 7;
        int base = bu * 512 + h * 64;
        int c0 = h * 64 + lane32, c1 = c0 + 32;
        float q0 = P.bq[c0], q1 = P.bq[c1];
        #pragma unroll
        for (int p = 0; p < 16; p++) {
            q0 += g_qp[p * QP + base + lane32];
            q1 += g_qp[p * QP + base + lane32 + 32];
        }
        g_q[base + lane32] = q0;
        g_q[base + lane32 + 32] = q1;
        float s = q0 * P.bk[c0] + q1 * P.bk[c1];
        #pragma unroll
        for (int off = 16; off; off >>= 1) s += __shfl_xor_sync(0xffffffffu, s, off);
        if (lane32 == 0) g_qbk[bu * 8 + h] = s;
    }
    grid_bar(nb);

    // ---- S3: Ak = (Wk_h^T q_h)*(1+mk)  per-head NT, K=64 -> 4 steps: 96 tiles ----
    for (int tt = bid; tt < 96; tt += nb) {
        int h = tt / 12, lt = tt % 12;
        int m0 = (lt & 1) * 128, n0 = (lt >> 1) * 128;
        gemm_ld<true, 128>(64, smA, smB,
            [&](int m, int k) { return ld4(&g_q[(m0 + m) * 512 + h * 64 + k]); },
            [&](int n, int k) { return ld4(&P.Wk[(n0 + n) * 512 + h * 64 + k]); },
            [&](int m, int n, float a) {
                int mg = m0 + m; int b = mg >> 6, u = mg & 63;
                long mi = (long)mg * 768 + n0 + n;
                g_Ak[b * 393216 + (h * 64 + u) * 768 + n0 + n] =
                    a * (1.f + g_mkp[mi] + g_mkp[196608 + mi] + g_mkp[2 * 196608 + mi]);
            });
    }
    grid_bar(nb);

    // ---- S4: score partials, K split x4 (K=192 -> 12 steps): 128 tiles ----
    for (int tt = bid; tt < 128; tt += nb) {
        int kp = tt >> 5, r = tt & 31;
        int b = r >> 3, l2 = r & 7;
        int m0 = (l2 & 3) * 128, n0 = (l2 >> 2) * 128, kb = kp * 192;
        gemm_ld<true, 128>(192, smA, smB,
            [&](int m, int k) { return ld4(&g_Ak[b * 393216 + (m0 + m) * 768 + kb + k]); },
            [&](int n, int k) { return ld4(&g_s[(b * 256 + n0 + n) * 768 + kb + k]); },
            [&](int m, int n, float a) {
                g_wp[kp * WP + b * 131072 + (m0 + m) * 256 + n0 + n] = a;
            });
    }
    grid_bar(nb);

    // ---- S5: softmax( (wp0..wp3+qbk)/8 ) -> g_w ----
    for (int r = wglob; r < 2048; r += nwarp) {
        int b = r >> 9, mg = r & 511;
        int h = mg >> 6, u = mg & 63;
        float qb = g_qbk[(b * 64 + u) * 8 + h];
        long base = (long)b * 131072 + (long)mg * 256;
        float v[8], mx = -1e30f;
        #pragma unroll
        for (int i = 0; i < 8; i++) {
            long idx = base + lane32 + 32 * i;
            v[i] = (g_wp[idx] + g_wp[WP + idx] + g_wp[2 * WP + idx] +
                    g_wp[3 * WP + idx] + qb) * 0.125f;
            mx = fmaxf(mx, v[i]);
        }
        #pragma unroll
        for (int off = 16; off; off >>= 1) mx = fmaxf(mx, __shfl_xor_sync(0xffffffffu, mx, off));
        float smv = 0.f;
        #pragma unroll
        for (int i = 0; i < 8; i++) { v[i] = expf(v[i] - mx); smv += v[i]; }
        #pragma unroll
        for (int off = 16; off; off >>= 1) smv += __shfl_xor_sync(0xffffffffu, smv, off);
        float inv = 1.f / smv;
        #pragma unroll
        for (int i = 0; i < 8; i++) g_w[base + lane32 + 32 * i] = v[i] * inv;
    }
    grid_bar(nb);

    // ---- S6: Tm = (w @ s)*(1+mv), per-head remap: K=256 -> 16 steps: 96 tiles ----
    for (int tt = bid; tt < 96; tt += nb) {
        int b = tt / 24, lt = tt % 24;
        int m0 = (lt & 3) * 128, n0 = (lt >> 2) * 128;
        gemm_ld<false, 128>(256, smA, smB,
            [&](int m, int k) { return ld4(&g_w[b * 131072 + (m0 + m) * 256 + k]); },
            [&](int k, int n) { return ld4(&g_s[(b * 256 + k) * 768 + n0 + n]); },
            [&](int m, int n, float a) {
                int mg = m0 + m; int h = mg >> 6, u = mg & 63; int bu = b * 64 + u;
                long mi = (long)bu * 768 + n0 + n;
                g_Tm[(h * 256 + bu) * 768 + n0 + n] =
                    a * (1.f + g_mvp[mi] + g_mvp[196608 + mi] + g_mvp[2 * 196608 + mi]);
            });
    }
    grid_bar(nb);

    // ---- S7: msg partials = Tm_h @ Wv_h, NTILE=64, K split x8 (K=96 -> 6): 128 tiles ----
    for (int tt = bid; tt < 128; tt += nb) {
        int kp = tt >> 4, lt = tt & 15;
        int h = lt >> 1, m0 = (lt & 1) * 128, kb = kp * 96;
        gemm_ld<false, 64>(96, smA, smB,
            [&](int m, int k) { return ld4(&g_Tm[(h * 256 + m0 + m) * 768 + kb + k]); },
            [&](int k, int n) { return ld4(&P.Wv[(kb + k) * 512 + h * 64 + n]); },
            [&](int m, int n, float a) {
                g_qp[kp * QP + (m0 + m) * 512 + h * 64 + n] = a;
            });
    }
    grid_bar(nb);

    // ---- S7b: msg = (sum(8 partials)+bv)*(1+me0+me1+me2) ----
    for (int i = gt; i < 32768; i += nth) {
        long idx = (long)i * 4;
        int c = (int)(idx & 511);
        float4 acc = ld4(&P.bv[c]);
        #pragma unroll
        for (int p = 0; p < 8; p++) {
            float4 v = ld4(&g_qp[p * QP + idx]);
            acc.x += v.x; acc.y += v.y; acc.z += v.z; acc.w += v.w;
        }
        float4 m0 = ld4(&g_mep[idx]), m1 = ld4(&g_mep[131072 + idx]);
        float4 m2 = ld4(&g_mep[2 * 131072 + idx]);
        float4 o;
        o.x = acc.x * (1.f + m0.x + m1.x + m2.x); o.y = acc.y * (1.f + m0.y + m1.y + m2.y);
        o.z = acc.z * (1.f + m0.z + m1.z + m2.z); o.w = acc.w * (1.f + m0.w + m1.w + m2.w);
        *(float4*)&g_msg[idx] = o;
    }
    grid_bar(nb);

    // ---- S8: out partials = msg @ We, K split x8 (K=64 -> 4 steps): 96 tiles ----
    for (int tt = bid; tt < 96; tt += nb) {
        int kp = tt / 12, lt = tt % 12;
        int m0 = (lt & 1) * 128, n0 = (lt >> 1) * 128, kb = kp * 64;
        gemm_ld<false, 128>(64, smA, smB,
            [&](int m, int k) { return ld4(&g_msg[(m0 + m) * 512 + kb + k]); },
            [&](int k, int n) { return ld4(&P.We[(kb + k) * 768 + n0 + n]); },
            [&](int m, int n, float a) {
                g_wp[kp * OP + (m0 + m) * 768 + n0 + n] = a;
            });
    }
    grid_bar(nb);

    // ---- S9: out = recv + (sum(8 partials)+be)*gamma ----
    for (int i = gt; i < 49152; i += nth) {
        long idx = (long)i * 4;
        int c = (int)(idx % 768);
        float4 acc = ld4(&P.be[c]);
        #pragma unroll
        for (int p = 0; p < 8; p++) {
            float4 v = ld4(&g_wp[p * OP + idx]);
            acc.x += v.x; acc.y += v.y; acc.z += v.z; acc.w += v.w;
        }
        float4 ga = ld4(&P.gamma[c]);
        float4 rv = ld4(&P.recv[idx]);
        float4 o;
        o.x = rv.x + acc.x * ga.x; o.y = rv.y + acc.y * ga.y;
        o.z = rv.z + acc.z * ga.z; o.w = rv.w + acc.w * ga.w;
        *(float4*)&P.out[idx] = o;
    }
}

// ---------------- Host launcher ----------------
extern "C" void kernel_launch(void* const* d_in, const int* in_sizes, int n_in,
                              void* d_out, int out_size) {
    (void)in_sizes; (void)n_in; (void)out_size;
    Params P;
    P.recv  = (const float*)d_in[0];
    P.codes = (const float*)d_in[1];
    P.send  = (const float*)d_in[2];
    P.lnrg  = (const float*)d_in[3];
    P.lnrb  = (const float*)d_in[4];
    P.lnsg  = (const float*)d_in[5];
    P.lnsb  = (const float*)d_in[6];
    P.Wq  = (const float*)d_in[7];
    P.bq  = (const float*)d_in[8];
    P.Wmq = (const float*)d_in[9];
    P.Wk  = (const float*)d_in[10];
    P.bk  = (const float*)d_in[11];
    P.Wmk = (const float*)d_in[12];
    P.Wv  = (const float*)d_in[13];
    P.bv  = (const float*)d_in[14];
    P.Wmv = (const float*)d_in[15];
    P.We  = (const float*)d_in[16];
    P.be  = (const float*)d_in[17];
    P.Wme = (const float*)d_in[18];
    P.gamma = (const float*)d_in[19];
    P.out = (float*)d_out;

    int occ = 0;
    cudaOccupancyMaxActiveBlocksPerMultiprocessor(&occ, fused_kernel, TPB, 0);
    if (occ < 1) occ = 1;
    int dev = 0;
    cudaGetDevice(&dev);
    int sms = 0;
    cudaDeviceGetAttribute(&sms, cudaDevAttrMultiProcessorCount, dev);
    if (sms < 1) sms = 1;
    int nb = occ * sms;
    if (nb > 1024) nb = 1024;
    P.nb = nb;

    fused_kernel<<<nb, TPB>>>(P);
}

// round 17
// speedup vs baseline: 1.0012x; 1.0012x over previous
#include <cuda_runtime.h>
#include <cuda_bf16.h>
#include <cstdint>

#define TPB 256
#define SASW 20            // words per smem row (32 bf16 + 8 pad)
#define ABUFW 1280         // 64 rows * 20 words per stage buffer

// B=4, U=64, V=256, DIM=768, CODE=384, INNER=512, HEADS=8, HD=64

struct Params {
    const float *recv, *codes, *send;
    const float *lnrg, *lnrb, *lnsg, *lnsb;
    const float *Wq, *bq, *Wmq, *Wk, *bk, *Wmk;
    const float *Wv, *bv, *Wmv, *We, *be, *Wme, *gamma;
    float* out;
    int nb;
};

typedef __nv_bfloat16 bf16;

// ---------------- Scratch (device globals; no allocs) ----------------
__device__ __align__(16) float g_r  [256 * 768];
__device__ __align__(16) float g_qbk[256 * 8];
// fp32 K-split partial buffers
__device__ __align__(16) float g_mqp[2 * 196608];
__device__ __align__(16) float g_mkp[2 * 196608];
__device__ __align__(16) float g_mvp[2 * 196608];
__device__ __align__(16) float g_mep[2 * 131072];
#define QP 131072
#define WP 524288
#define OP 196608
__device__ __align__(16) float g_qp[8 * QP];
__device__ __align__(16) float g_wp[3 * WP];
// bf16 GEMM operands (intermediates)
__device__ __align__(16) bf16 g_sbf [1024 * 768];       // LN(sender), [v-major][i]
__device__ __align__(16) bf16 g_sT  [4 * 768 * 256];    // per-batch transposed [i][v]
__device__ __align__(16) bf16 g_rqb [256 * 768];
__device__ __align__(16) bf16 g_qb  [256 * 512];
__device__ __align__(16) bf16 g_Akb [4 * 512 * 768];
__device__ __align__(16) bf16 g_wb  [4 * 512 * 256];
__device__ __align__(16) bf16 g_Tmb [8 * 256 * 768];
__device__ __align__(16) bf16 g_msgb[256 * 512];
// bf16 weights (converted / transposed in S0)
__device__ __align__(16) bf16 w_cod [256 * 384];
__device__ __align__(16) bf16 w_mqT [768 * 384];
__device__ __align__(16) bf16 w_mkT [768 * 384];
__device__ __align__(16) bf16 w_mvT [768 * 384];
__device__ __align__(16) bf16 w_meT [512 * 384];
__device__ __align__(16) bf16 w_qT  [512 * 768];
__device__ __align__(16) bf16 w_k   [768 * 512];        // natural layout (already [n][k])
__device__ __align__(16) bf16 w_vT  [512 * 768];
__device__ __align__(16) bf16 w_eT  [768 * 512];

__device__ unsigned g_barcnt = 0;
__device__ unsigned g_bargen = 0;

__device__ __forceinline__ void grid_bar(int nb) {
    __syncthreads();
    if (threadIdx.x == 0) {
        __threadfence();
        unsigned gen = *(volatile unsigned*)&g_bargen;
        unsigned t = atomicAdd(&g_barcnt, 1u);
        if (t == (unsigned)(nb - 1)) {
            atomicExch(&g_barcnt, 0u);
            __threadfence();
            atomicExch(&g_bargen, gen + 1u);
        } else {
            while (*(volatile unsigned*)&g_bargen == gen) { __nanosleep(32); }
        }
        __threadfence();
    }
    __syncthreads();
}

// ---------------- helpers ----------------
__device__ __forceinline__ void mma16(float* c, const uint32_t* a, const uint32_t* b) {
    asm volatile(
        "mma.sync.aligned.m16n8k16.row.col.f32.bf16.bf16.f32 "
        "{%0,%1,%2,%3}, {%4,%5,%6,%7}, {%8,%9}, {%0,%1,%2,%3};"
        : "+f"(c[0]), "+f"(c[1]), "+f"(c[2]), "+f"(c[3])
        : "r"(a[0]), "r"(a[1]), "r"(a[2]), "r"(a[3]), "r"(b[0]), "r"(b[1]));
}
__device__ __forceinline__ void cp16(uint32_t dst, const void* src) {
    asm volatile("cp.async.cg.shared.global [%0], [%1], 16;\n"
                 :: "r"(dst), "l"(src) : "memory");
}
__device__ __forceinline__ void cp_commit() {
    asm volatile("cp.async.commit_group;\n" ::: "memory");
}
__device__ __forceinline__ void cp_wait2() {
    asm volatile("cp.async.wait_group 2;\n" ::: "memory");
}
__device__ __forceinline__ float4 ld4(const float* p) { return *(const float4*)p; }
__device__ __forceinline__ bf16 fb(float x) { return __float2bfloat16_rn(x); }

// ---- block 64x64 bf16 GEMM, K=32 chunks, 4-stage cp.async (R10 schedule) ----
// C(m,n) = sum_k A(m,k)*B(k,n); K%32==0, K>=64.
// la(r) -> const bf16* base of A row r (tile k-origin); lb(r) -> B row r ([n][k]).
template<class LA, class LB, class EP>
__device__ __forceinline__ void gemm_bf(int K, uint32_t* smA, uint32_t* smB,
                                        uint32_t saA, uint32_t saB,
                                        LA la, LB lb, EP ep) {
    const int tid = threadIdx.x;
    const int l = tid & 31, g = l >> 2, t = l & 3;
    const int wid = tid >> 5;
    const int wm0 = (wid & 1) * 32, wn0 = (wid >> 1) * 16;
    const int fr = tid >> 2, fs = tid & 3;   // fill: row 0..63, 16B segment 0..3
    const int ns = K / 32;

    const uint32_t dA = saA + (uint32_t)(fr * SASW + fs * 4) * 4u;
    const uint32_t dB = saB + (uint32_t)(fr * SASW + fs * 4) * 4u;

    auto issue = [&](int s) {
        int buf = s & 3;
        int k0 = s * 32;
        cp16(dA + buf * (ABUFW * 4u), la(fr) + k0 + fs * 8);
        cp16(dB + buf * (ABUFW * 4u), lb(fr) + k0 + fs * 8);
        cp_commit();
    };

    float acc[2][2][4];
    #pragma unroll
    for (int i = 0; i < 2; i++)
        #pragma unroll
        for (int j = 0; j < 2; j++)
            #pragma unroll
            for (int e = 0; e < 4; e++) acc[i][j][e] = 0.f;

    issue(0); issue(1); issue(2);
    cp_wait2();
    __syncthreads();

    for (int s = 0; s < ns; s++) {
        if (s + 3 < ns) issue(s + 3); else cp_commit();
        const uint32_t* __restrict__ A = smA + (s & 3) * ABUFW;
        const uint32_t* __restrict__ B = smB + (s & 3) * ABUFW;
        #pragma unroll
        for (int kw = 0; kw < 16; kw += 8) {   // two k16 groups per K=32 chunk
            uint32_t af[2][4], bfr[2][2];
            #pragma unroll
            for (int mi = 0; mi < 2; mi++) {
                int mb = wm0 + mi * 16;
                af[mi][0] = A[(mb + g) * SASW + kw + t];
                af[mi][1] = A[(mb + 8 + g) * SASW + kw + t];
                af[mi][2] = A[(mb + g) * SASW + kw + 4 + t];
                af[mi][3] = A[(mb + 8 + g) * SASW + kw + 4 + t];
            }
            #pragma unroll
            for (int ni = 0; ni < 2; ni++) {
                int nn = wn0 + ni * 8 + g;
                bfr[ni][0] = B[nn * SASW + kw + t];
                bfr[ni][1] = B[nn * SASW + kw + 4 + t];
            }
            #pragma unroll
            for (int mi = 0; mi < 2; mi++)
                #pragma unroll
                for (int ni = 0; ni < 2; ni++)
                    mma16(acc[mi][ni], af[mi], bfr[ni]);
        }
        cp_wait2();
        __syncthreads();
    }

    #pragma unroll
    for (int mi = 0; mi < 2; mi++)
        #pragma unroll
        for (int ni = 0; ni < 2; ni++) {
            int r = wm0 + mi * 16 + g, c = wn0 + ni * 8 + 2 * t;
            ep(r,     c,     acc[mi][ni][0]);
            ep(r,     c + 1, acc[mi][ni][1]);
            ep(r + 8, c,     acc[mi][ni][2]);
            ep(r + 8, c + 1, acc[mi][ni][3]);
        }
}

// ---------------- The single persistent kernel ----------------
__global__ void __launch_bounds__(TPB, 3) fused_kernel(Params P) {
    __shared__ __align__(16) uint32_t smA[4 * ABUFW];
    __shared__ __align__(16) uint32_t smB[4 * ABUFW];
    const uint32_t saA = (uint32_t)__cvta_generic_to_shared(smA);
    const uint32_t saB = (uint32_t)__cvta_generic_to_shared(smB);
    const int nb = P.nb;
    const int bid = blockIdx.x;
    const int wglob = bid * 8 + (threadIdx.x >> 5);
    const int nwarp = nb * 8;
    const int lane32 = threadIdx.x & 31;
    const int nth = nwarp * 32;
    const int gt = wglob * 32 + lane32;

    // ---- S0: LayerNorms + bf16 weight conversion/transposition ----
    for (int r = wglob; r < 1280; r += nwarp) {
        if (r < 256) {
            // receiver LN -> fp32 g_r
            const float* x = P.recv + r * 768;
            float v[24], s = 0.f, q = 0.f;
            #pragma unroll
            for (int i = 0; i < 24; i++) {
                v[i] = x[lane32 + 32 * i]; s += v[i]; q += v[i] * v[i];
            }
            #pragma unroll
            for (int off = 16; off; off >>= 1) {
                s += __shfl_xor_sync(0xffffffffu, s, off);
                q += __shfl_xor_sync(0xffffffffu, q, off);
            }
            float mu = s * (1.f / 768.f);
            float inv = rsqrtf(q * (1.f / 768.f) - mu * mu + 1e-5f);
            float* o = g_r + r * 768;
            #pragma unroll
            for (int i = 0; i < 24; i++) {
                int idx = lane32 + 32 * i;
                o[idx] = (v[i] - mu) * inv * P.lnrg[idx] + P.lnrb[idx];
            }
        } else {
            // sender LN -> bf16 g_sbf + transposed g_sT
            int rr = r - 256;                 // 0..1023 = b*256+v
            int b = rr >> 8, vv = rr & 255;
            const float* x = P.send + rr * 768;
            float v[24], s = 0.f, q = 0.f;
            #pragma unroll
            for (int i = 0; i < 24; i++) {
                v[i] = x[lane32 + 32 * i]; s += v[i]; q += v[i] * v[i];
            }
            #pragma unroll
            for (int off = 16; off; off >>= 1) {
                s += __shfl_xor_sync(0xffffffffu, s, off);
                q += __shfl_xor_sync(0xffffffffu, q, off);
            }
            float mu = s * (1.f / 768.f);
            float inv = rsqrtf(q * (1.f / 768.f) - mu * mu + 1e-5f);
            bf16* o = g_sbf + (long)rr * 768;
            bf16* oT = g_sT + (long)b * 196608 + vv;
            #pragma unroll
            for (int i = 0; i < 24; i++) {
                int idx = lane32 + 32 * i;
                float val = (v[i] - mu) * inv * P.lnsg[idx] + P.lnsb[idx];
                bf16 bv = fb(val);
                o[idx] = bv;
                oT[(long)idx * 256] = bv;
            }
        }
    }
    // weight conversions
    for (int i = gt; i < 98304; i += nth) w_cod[i] = fb(P.codes[i]);
    for (int i = gt; i < 393216; i += nth) w_k[i] = fb(P.Wk[i]);
    for (int i = gt; i < 393216; i += nth) {
        int k = i >> 9, n = i & 511;        // Wq [768][512]
        w_qT[n * 768 + k] = fb(P.Wq[i]);
        w_vT[n * 768 + k] = fb(P.Wv[i]);
    }
    for (int i = gt; i < 393216; i += nth) {
        int k = i / 768, n = i % 768;       // We [512][768]
        w_eT[n * 512 + k] = fb(P.We[i]);
    }
    for (int i = gt; i < 294912; i += nth) {
        int k = i / 768, n = i % 768;       // Wm* [384][768]
        w_mqT[n * 384 + k] = fb(P.Wmq[i]);
        w_mkT[n * 384 + k] = fb(P.Wmk[i]);
        w_mvT[n * 384 + k] = fb(P.Wmv[i]);
    }
    for (int i = gt; i < 196608; i += nth) {
        int k = i >> 9, n = i & 511;        // Wme [384][512]
        w_meT[n * 384 + k] = fb(P.Wme[i]);
    }
    grid_bar(nb);

    // ---- S1: 4 modulation GEMMs, K split x2 (K=192 -> 6 steps): 352 tiles ----
    for (int tt = bid; tt < 352; tt += nb) {
        const bf16* W; float* O; int N, lt, kp;
        if (tt < 288) {
            int sel = tt / 96, r = tt % 96;
            kp = r / 48; lt = r % 48; N = 768;
            W = sel == 0 ? w_mqT : (sel == 1 ? w_mkT : w_mvT);
            O = (sel == 0 ? g_mqp : (sel == 1 ? g_mkp : g_mvp)) + kp * 196608;
        } else {
            int r = tt - 288;
            kp = r / 32; lt = r % 32; N = 512;
            W = w_meT; O = g_mep + kp * 131072;
        }
        int m0 = (lt & 3) * 64, n0 = (lt >> 2) * 64, kb = kp * 192;
        gemm_bf(192, smA, smB, saA, saB,
            [&](int r) { return w_cod + (m0 + r) * 384 + kb; },
            [&](int r) { return W + (n0 + r) * 384 + kb; },
            [&](int m, int n, float a) { O[(long)(m0 + m) * N + n0 + n] = a; });
    }
    grid_bar(nb);

    // ---- S1b: rq = bf16( r * (1 + mqp0 + mqp1) ) ----
    for (int i = gt; i < 196608; i += nth) {
        float a = g_mqp[i] + g_mqp[196608 + i];
        g_rqb[i] = fb(g_r[i] * (1.f + a));
    }
    grid_bar(nb);

    // ---- S2: q partials, K split x8 (K=96 -> 3 steps): 256 tiles ----
    for (int tt = bid; tt < 256; tt += nb) {
        int kp = tt >> 5, lt = tt & 31;
        int m0 = (lt & 3) * 64, n0 = (lt >> 2) * 64, kb = kp * 96;
        gemm_bf(96, smA, smB, saA, saB,
            [&](int r) { return g_rqb + (m0 + r) * 768 + kb; },
            [&](int r) { return w_qT + (n0 + r) * 768 + kb; },
            [&](int m, int n, float a) { g_qp[kp * QP + (m0 + m) * 512 + n0 + n] = a; });
    }
    grid_bar(nb);

    // ---- S2b: q = sum(8 partials)+bq -> bf16 ; qbk = q . bk (fp32) ----
    for (int w = wglob; w < 2048; w += nwarp) {
        int bu = w >> 3, h = w & 7;
        int base = bu * 512 + h * 64;
        int c0 = h * 64 + lane32, c1 = c0 + 32;
        float q0 = P.bq[c0], q1 = P.bq[c1];
        #pragma unroll
        for (int p = 0; p < 8; p++) {
            q0 += g_qp[p * QP + base + lane32];
            q1 += g_qp[p * QP + base + lane32 + 32];
        }
        g_qb[base + lane32] = fb(q0);
        g_qb[base + lane32 + 32] = fb(q1);
        float s = q0 * P.bk[c0] + q1 * P.bk[c1];
        #pragma unroll
        for (int off = 16; off; off >>= 1) s += __shfl_xor_sync(0xffffffffu, s, off);
        if (lane32 == 0) g_qbk[bu * 8 + h] = s;
    }
    grid_bar(nb);

    // ---- S3: Ak = bf16( (Wk_h^T q_h)*(1+mk) )  per-head, K=64 -> 2 steps: 384 tiles ----
    for (int tt = bid; tt < 384; tt += nb) {
        int h = tt / 48, lt = tt % 48;
        int m0 = (lt & 3) * 64, n0 = (lt >> 2) * 64;
        gemm_bf(64, smA, smB, saA, saB,
            [&](int r) { return g_qb + (m0 + r) * 512 + h * 64; },
            [&](int r) { return w_k + (n0 + r) * 512 + h * 64; },
            [&](int m, int n, float a) {
                int mg = m0 + m; int b = mg >> 6, u = mg & 63;
                long mi = (long)mg * 768 + n0 + n;
                g_Akb[(long)b * 393216 + (long)(h * 64 + u) * 768 + n0 + n] =
                    fb(a * (1.f + g_mkp[mi] + g_mkp[196608 + mi]));
            });
    }
    grid_bar(nb);

    // ---- S4: score partials, K split x3 (K=256 -> 8 steps): 384 tiles ----
    for (int tt = bid; tt < 384; tt += nb) {
        int kp = tt >> 7, lt = tt & 127;
        int b = lt >> 5, l2 = lt & 31;
        int m0 = (l2 & 7) * 64, n0 = (l2 >> 3) * 64, kb = kp * 256;
        gemm_bf(256, smA, smB, saA, saB,
            [&](int r) { return g_Akb + (long)b * 393216 + (long)(m0 + r) * 768 + kb; },
            [&](int r) { return g_sbf + (long)(b * 256 + n0 + r) * 768 + kb; },
            [&](int m, int n, float a) {
                g_wp[kp * WP + b * 131072 + (m0 + m) * 256 + n0 + n] = a;
            });
    }
    grid_bar(nb);

    // ---- S5: softmax( (wp0+wp1+wp2+qbk)/8 ) -> bf16 g_wb ----
    for (int r = wglob; r < 2048; r += nwarp) {
        int b = r >> 9, mg = r & 511;
        int h = mg >> 6, u = mg & 63;
        float qb = g_qbk[(b * 64 + u) * 8 + h];
        long base = (long)b * 131072 + (long)mg * 256;
        float v[8], mx = -1e30f;
        #pragma unroll
        for (int i = 0; i < 8; i++) {
            long idx = base + lane32 + 32 * i;
            v[i] = (g_wp[idx] + g_wp[WP + idx] + g_wp[2 * WP + idx] + qb) * 0.125f;
            mx = fmaxf(mx, v[i]);
        }
        #pragma unroll
        for (int off = 16; off; off >>= 1) mx = fmaxf(mx, __shfl_xor_sync(0xffffffffu, mx, off));
        float smv = 0.f;
        #pragma unroll
        for (int i = 0; i < 8; i++) { v[i] = expf(v[i] - mx); smv += v[i]; }
        #pragma unroll
        for (int off = 16; off; off >>= 1) smv += __shfl_xor_sync(0xffffffffu, smv, off);
        float inv = 1.f / smv;
        #pragma unroll
        for (int i = 0; i < 8; i++) g_wb[base + lane32 + 32 * i] = fb(v[i] * inv);
    }
    grid_bar(nb);

    // ---- S6: Tm = bf16( (w @ s)*(1+mv) ), per-head remap: K=256 -> 8 steps: 384 tiles ----
    for (int tt = bid; tt < 384; tt += nb) {
        int b = tt / 96, lt = tt % 96;
        int m0 = (lt & 7) * 64, n0 = (lt >> 3) * 64;
        gemm_bf(256, smA, smB, saA, saB,
            [&](int r) { return g_wb + (long)b * 131072 + (long)(m0 + r) * 256; },
            [&](int r) { return g_sT + (long)b * 196608 + (long)(n0 + r) * 256; },
            [&](int m, int n, float a) {
                int mg = m0 + m; int h = mg >> 6, u = mg & 63; int bu = b * 64 + u;
                long mi = (long)bu * 768 + n0 + n;
                g_Tmb[(long)(h * 256 + bu) * 768 + n0 + n] =
                    fb(a * (1.f + g_mvp[mi] + g_mvp[196608 + mi]));
            });
    }
    grid_bar(nb);

    // ---- S7: msg partials = Tm_h @ Wv_h, K split x8 (K=96 -> 3 steps): 256 tiles ----
    for (int tt = bid; tt < 256; tt += nb) {
        int kp = tt >> 5, lt = tt & 31;
        int h = lt >> 2, m0 = (lt & 3) * 64, kb = kp * 96;
        gemm_bf(96, smA, smB, saA, saB,
            [&](int r) { return g_Tmb + (long)(h * 256 + m0 + r) * 768 + kb; },
            [&](int r) { return w_vT + (long)(h * 64 + r) * 768 + kb; },
            [&](int m, int n, float a) {
                g_qp[kp * QP + (m0 + m) * 512 + h * 64 + n] = a;
            });
    }
    grid_bar(nb);

    // ---- S7b: msg = bf16( (sum(8 partials)+bv)*(1+me0+me1) ) ----
    for (int i = gt; i < 131072; i += nth) {
        int c = i & 511;
        float acc = P.bv[c];
        #pragma unroll
        for (int p = 0; p < 8; p++) acc += g_qp[p * QP + i];
        float me = g_mep[i] + g_mep[131072 + i];
        g_msgb[i] = fb(acc * (1.f + me));
    }
    grid_bar(nb);

    // ---- S8: out partials = msg @ We, K split x8 (K=64 -> 2 steps): 384 tiles ----
    for (int tt = bid; tt < 384; tt += nb) {
        int kp = tt / 48, lt = tt % 48;
        int m0 = (lt & 3) * 64, n0 = (lt >> 2) * 64, kb = kp * 64;
        gemm_bf(64, smA, smB, saA, saB,
            [&](int r) { return g_msgb + (m0 + r) * 512 + kb; },
            [&](int r) { return w_eT + (n0 + r) * 512 + kb; },
            [&](int m, int n, float a) {
                g_wp[kp * OP + (m0 + m) * 768 + n0 + n] = a;
            });
    }
    grid_bar(nb);

    // ---- S9: out = recv + (sum(8 partials)+be)*gamma ----
    for (int i = gt; i < 49152; i += nth) {
        long idx = (long)i * 4;
        int c = (int)(idx % 768);
        float4 acc = ld4(&P.be[c]);
        #pragma unroll
        for (int p = 0; p < 8; p++) {
            float4 v = ld4(&g_wp[p * OP + idx]);
            acc.x += v.x; acc.y += v.y; acc.z += v.z; acc.w += v.w;
        }
        float4 ga = ld4(&P.gamma[c]);
        float4 rv = ld4(&P.recv[idx]);
        float4 o;
        o.x = rv.x + acc.x * ga.x; o.y = rv.y + acc.y * ga.y;
        o.z = rv.z + acc.z * ga.z; o.w = rv.w + acc.w * ga.w;
        *(float4*)&P.out[idx] = o;
    }
}

// ---------------- Host launcher ----------------
extern "C" void kernel_launch(void* const* d_in, const int* in_sizes, int n_in,
                              void* d_out, int out_size) {
    (void)in_sizes; (void)n_in; (void)out_size;
    Params P;
    P.recv  = (const float*)d_in[0];
    P.codes = (const float*)d_in[1];
    P.send  = (const float*)d_in[2];
    P.lnrg  = (const float*)d_in[3];
    P.lnrb  = (const float*)d_in[4];
    P.lnsg  = (const float*)d_in[5];
    P.lnsb  = (const float*)d_in[6];
    P.Wq  = (const float*)d_in[7];
    P.bq  = (const float*)d_in[8];
    P.Wmq = (const float*)d_in[9];
    P.Wk  = (const float*)d_in[10];
    P.bk  = (const float*)d_in[11];
    P.Wmk = (const float*)d_in[12];
    P.Wv  = (const float*)d_in[13];
    P.bv  = (const float*)d_in[14];
    P.Wmv = (const float*)d_in[15];
    P.We  = (const float*)d_in[16];
    P.be  = (const float*)d_in[17];
    P.Wme = (const float*)d_in[18];
    P.gamma = (const float*)d_in[19];
    P.out = (float*)d_out;

    int occ = 0;
    cudaOccupancyMaxActiveBlocksPerMultiprocessor(&occ, fused_kernel, TPB, 0);
    if (occ < 1) occ = 1;
    int dev = 0;
    cudaGetDevice(&dev);
    int sms = 0;
    cudaDeviceGetAttribute(&sms, cudaDevAttrMultiProcessorCount, dev);
    if (sms < 1) sms = 1;
    int nb = occ * sms;
    if (nb > 1024) nb = 1024;
    P.nb = nb;

    fused_kernel<<<nb, TPB>>>(P);
}